// round 15
// baseline (speedup 1.0000x reference)
#include <cuda_runtime.h>
#include <cuda_bf16.h>

#define NN 50000
#define EE 1600000
#define FULL 0xffffffffu

typedef unsigned long long u64t;
typedef unsigned int u32;

__device__ __forceinline__ u64t pk(float lo, float hi) {
    u64t r; asm("mov.b64 %0,{%1,%2};" : "=l"(r) : "f"(lo), "f"(hi)); return r;
}
__device__ __forceinline__ void upk(u64t v, float& lo, float& hi) {
    asm("mov.b64 {%0,%1},%2;" : "=f"(lo), "=f"(hi) : "l"(v));
}
__device__ __forceinline__ u64t f2fma(u64t a, u64t b, u64t c) {
    u64t d; asm("fma.rn.f32x2 %0,%1,%2,%3;" : "=l"(d) : "l"(a), "l"(b), "l"(c)); return d;
}
__device__ __forceinline__ float4 ldcs4f(const float4* p) {
    float4 r;
    asm("ld.global.cs.v4.f32 {%0,%1,%2,%3},[%4];"
        : "=f"(r.x), "=f"(r.y), "=f"(r.z), "=f"(r.w) : "l"(p));
    return r;
}
__device__ __forceinline__ u32 ldcs1u(const u32* p) {
    u32 r; asm("ld.global.cs.u32 %0,[%1];" : "=r"(r) : "l"(p)); return r;
}
__device__ __forceinline__ void stcs4u(u32* p, u32 a, u32 b, u32 c, u32 d) {
    asm("st.global.cs.v4.u32 [%0],{%1,%2,%3,%4};"
        :: "l"(p), "r"(a), "r"(b), "r"(c), "r"(d) : "memory");
}
// bf16x2 packed fma (elementwise; accumulate in bf16x2)
__device__ __forceinline__ u32 bffma2(u32 a, u32 b, u32 c) {
    u32 d; asm("fma.rn.bf16x2 %0,%1,%2,%3;" : "=r"(d) : "r"(a), "r"(b), "r"(c)); return d;
}
__device__ __forceinline__ float bfsum2(u32 v) {
    float lo = __uint_as_float(v << 16);
    float hi = __uint_as_float(v & 0xffff0000u);
    return lo + hi;
}
// pack two floats into bf16x2 {lo, hi}
__device__ __forceinline__ u32 f2bf2(float lo, float hi) {
    u32 r; asm("cvt.rn.bf16x2.f32 %0,%1,%2;" : "=r"(r) : "f"(hi), "f"(lo)); return r;
}
// expand bf16x2 -> f32x2 (exact)
__device__ __forceinline__ u64t bf2f2(u32 v) {
    return pk(__uint_as_float(v << 16), __uint_as_float(v & 0xffff0000u));
}

// ---------------- scratch ----------------------------------------------------
__device__ __nv_bfloat16 g_q1b[NN*128];   // pre-scaled by 1/sqrt(32)
__device__ __nv_bfloat16 g_k1b[NN*128];
__device__ __nv_bfloat16 g_t1b[NN*256];
__device__ __nv_bfloat16 g_v1b[NN*128];
__device__ __nv_bfloat16 g_q2b[NN*64];    // pre-scaled by 0.125
__device__ __nv_bfloat16 g_k2b[NN*64];
__device__ __nv_bfloat16 g_t2b[NN*64];
__device__ __nv_bfloat16 g_v2b[NN*64];
__device__ __nv_bfloat16 g_efb[(size_t)EE*64];  // ef in bf16, CSR-slot order
__device__ float g_h [NN*128];
__device__ float g_s2[NN*64];
__device__ float g_w [EE*4];
__device__ int   g_cnt[NN];
__device__ int   g_rowptr[NN+1];
__device__ int   g_woff[NN];
__device__ int   g_bsum[64];
__device__ int2  g_edges[EE];
__device__ int   g_edst[EE];

// ---------------- CSR build ---------------------------------------------------
__global__ void k_zero_cnt() {
    int i = blockIdx.x*blockDim.x + threadIdx.x;
    if (i < NN) g_cnt[i] = 0;
}
__global__ void k_hist(const int* __restrict__ dst) {
    int e = blockIdx.x*blockDim.x + threadIdx.x;
    if (e < EE) atomicAdd(&g_cnt[dst[e]], 1);
}
__global__ void k_scanA() {
    __shared__ int s[1024];
    int b = blockIdx.x;
    int i = b*1024 + threadIdx.x;
    int v = (i < NN) ? g_cnt[i] : 0;
    s[threadIdx.x] = v;
    __syncthreads();
    for (int off = 1; off < 1024; off <<= 1) {
        int t = (threadIdx.x >= off) ? s[threadIdx.x - off] : 0;
        __syncthreads();
        s[threadIdx.x] += t;
        __syncthreads();
    }
    if (i < NN) g_rowptr[i] = s[threadIdx.x] - v;
    if (threadIdx.x == 1023) g_bsum[b] = s[1023];
}
__global__ void k_scanB() {
    __shared__ int s[64];
    int t = threadIdx.x;
    int v = (t < 49) ? g_bsum[t] : 0;
    s[t] = v;
    __syncthreads();
    for (int off = 1; off < 64; off <<= 1) {
        int x = (t >= off) ? s[t - off] : 0;
        __syncthreads();
        s[t] += x;
        __syncthreads();
    }
    if (t < 49) g_bsum[t] = s[t] - v;
    if (t == 48) g_rowptr[NN] = s[48];
}
__global__ void k_scanC() {
    int i = blockIdx.x*blockDim.x + threadIdx.x;
    if (i < NN) {
        int r = g_rowptr[i] + g_bsum[i >> 10];
        g_rowptr[i] = r;
        g_woff[i] = r;
    }
}
__global__ void k_scatter(const int* __restrict__ src, const int* __restrict__ dst) {
    int e = blockIdx.x*blockDim.x + threadIdx.x;
    if (e < EE) {
        int d = dst[e];
        int p = atomicAdd(&g_woff[d], 1);
        g_edges[p] = make_int2(src[e], e);
        g_edst[p] = d;
    }
}

// ---------------- node linear layer 1 ------------------------------------------
// mats 0,1,2 (q,k,v) -> bf16 (q pre-scaled); mat 3 (skip) -> fp32
__global__ void __launch_bounds__(256) k_node1(const float* __restrict__ x,
    const float* __restrict__ Wq, const float* __restrict__ bq,
    const float* __restrict__ Wk, const float* __restrict__ bk,
    const float* __restrict__ Wv, const float* __restrict__ bv,
    const float* __restrict__ Ws, const float* __restrict__ bs)
{
    const int CIN = 128, COUT = 128, BN = 64, KC = 16;
    int mat = blockIdx.y;
    const float* W = (mat==0)?Wq:((mat==1)?Wk:((mat==2)?Wv:Ws));
    const float* b = (mat==0)?bq:((mat==1)?bk:((mat==2)?bv:bs));
    int n0 = blockIdx.x * BN;
    int tid = threadIdx.x;
    int lane = tid & 31, ty = tid >> 5;

    __shared__ float xs[CIN][BN];
    __shared__ float ws2[KC][2*COUT];

    for (int i = tid; i < BN*CIN; i += 256) {
        int nn = i >> 7, c = i & 127;
        xs[c][nn] = (n0+nn < NN) ? x[(size_t)(n0+nn)*CIN + c] : 0.f;
    }

    u64t acc[4][4];
    #pragma unroll
    for (int c = 0; c < 4; c++) {
        float bc = b[lane + 32*c];
        u64t bp = pk(bc, bc);
        acc[0][c] = bp; acc[1][c] = bp; acc[2][c] = bp; acc[3][c] = bp;
    }

    for (int kc = 0; kc < CIN; kc += KC) {
        __syncthreads();
        for (int i = tid; i < KC*COUT; i += 256) {
            int kk = i >> 7, c = i & 127;
            float w = W[(size_t)(kc+kk)*COUT + c];
            *(float2*)&ws2[kk][2*c] = make_float2(w, w);
        }
        __syncthreads();
        #pragma unroll 4
        for (int kk = 0; kk < KC; kk++) {
            const u64t* xr = (const u64t*)&xs[kc+kk][ty*8];
            u64t x0 = xr[0], x1 = xr[1], x2 = xr[2], x3 = xr[3];
            const u64t* wr = (const u64t*)ws2[kk];
            u64t w0 = wr[lane], w1 = wr[lane+32], w2 = wr[lane+64], w3 = wr[lane+96];
            acc[0][0]=f2fma(x0,w0,acc[0][0]); acc[0][1]=f2fma(x0,w1,acc[0][1]);
            acc[0][2]=f2fma(x0,w2,acc[0][2]); acc[0][3]=f2fma(x0,w3,acc[0][3]);
            acc[1][0]=f2fma(x1,w0,acc[1][0]); acc[1][1]=f2fma(x1,w1,acc[1][1]);
            acc[1][2]=f2fma(x1,w2,acc[1][2]); acc[1][3]=f2fma(x1,w3,acc[1][3]);
            acc[2][0]=f2fma(x2,w0,acc[2][0]); acc[2][1]=f2fma(x2,w1,acc[2][1]);
            acc[2][2]=f2fma(x2,w2,acc[2][2]); acc[2][3]=f2fma(x2,w3,acc[2][3]);
            acc[3][0]=f2fma(x3,w0,acc[3][0]); acc[3][1]=f2fma(x3,w1,acc[3][1]);
            acc[3][2]=f2fma(x3,w2,acc[3][2]); acc[3][3]=f2fma(x3,w3,acc[3][3]);
        }
    }
    if (mat < 3) {
        __nv_bfloat16* ob = (mat==0) ? g_q1b : ((mat==1) ? g_k1b : g_v1b);
        float sc = (mat==0) ? 0.1767766952966369f : 1.f;
        #pragma unroll
        for (int j = 0; j < 4; j++) {
            int r0 = n0 + ty*8 + 2*j, r1 = r0 + 1;
            #pragma unroll
            for (int c = 0; c < 4; c++) {
                float a0, a1; upk(acc[j][c], a0, a1);
                if (r0 < NN) ob[(size_t)r0*COUT + lane + 32*c] = __float2bfloat16(a0*sc);
                if (r1 < NN) ob[(size_t)r1*COUT + lane + 32*c] = __float2bfloat16(a1*sc);
            }
        }
    } else {
        #pragma unroll
        for (int j = 0; j < 4; j++) {
            int r0 = n0 + ty*8 + 2*j, r1 = r0 + 1;
            #pragma unroll
            for (int c = 0; c < 4; c++) {
                float a0, a1; upk(acc[j][c], a0, a1);
                if (r0 < NN) g_h[(size_t)r0*COUT + lane + 32*c] = a0;
                if (r1 < NN) g_h[(size_t)r1*COUT + lane + 32*c] = a1;
            }
        }
    }
}

__global__ void __launch_bounds__(256) k_node2(
    const float* __restrict__ Wq, const float* __restrict__ bq,
    const float* __restrict__ Wk, const float* __restrict__ bk,
    const float* __restrict__ Wv, const float* __restrict__ bv,
    const float* __restrict__ Ws, const float* __restrict__ bs)
{
    const int CIN = 128, COUT = 64, BN = 64, KC = 16;
    int mat = blockIdx.y;
    const float* W = (mat==0)?Wq:((mat==1)?Wk:((mat==2)?Wv:Ws));
    const float* b = (mat==0)?bq:((mat==1)?bk:((mat==2)?bv:bs));
    int n0 = blockIdx.x * BN;
    int tid = threadIdx.x;
    int lane = tid & 31, ty = tid >> 5;

    __shared__ float xs[CIN][BN];
    __shared__ float ws2[KC][2*COUT];

    for (int i = tid; i < BN*CIN; i += 256) {
        int nn = i >> 7, c = i & 127;
        xs[c][nn] = (n0+nn < NN) ? g_h[(size_t)(n0+nn)*CIN + c] : 0.f;
    }

    u64t acc[4][2];
    #pragma unroll
    for (int c = 0; c < 2; c++) {
        float bc = b[lane + 32*c];
        u64t bp = pk(bc, bc);
        acc[0][c] = bp; acc[1][c] = bp; acc[2][c] = bp; acc[3][c] = bp;
    }

    for (int kc = 0; kc < CIN; kc += KC) {
        __syncthreads();
        for (int i = tid; i < KC*COUT; i += 256) {
            int kk = i >> 6, c = i & 63;
            float w = W[(size_t)(kc+kk)*COUT + c];
            *(float2*)&ws2[kk][2*c] = make_float2(w, w);
        }
        __syncthreads();
        #pragma unroll 4
        for (int kk = 0; kk < KC; kk++) {
            const u64t* xr = (const u64t*)&xs[kc+kk][ty*8];
            u64t x0 = xr[0], x1 = xr[1], x2 = xr[2], x3 = xr[3];
            const u64t* wr = (const u64t*)ws2[kk];
            u64t w0 = wr[lane], w1 = wr[lane+32];
            acc[0][0]=f2fma(x0,w0,acc[0][0]); acc[0][1]=f2fma(x0,w1,acc[0][1]);
            acc[1][0]=f2fma(x1,w0,acc[1][0]); acc[1][1]=f2fma(x1,w1,acc[1][1]);
            acc[2][0]=f2fma(x2,w0,acc[2][0]); acc[2][1]=f2fma(x2,w1,acc[2][1]);
            acc[3][0]=f2fma(x3,w0,acc[3][0]); acc[3][1]=f2fma(x3,w1,acc[3][1]);
        }
    }
    if (mat < 3) {
        __nv_bfloat16* ob = (mat==0) ? g_q2b : ((mat==1) ? g_k2b : g_v2b);
        float sc = (mat==0) ? 0.125f : 1.f;
        #pragma unroll
        for (int j = 0; j < 4; j++) {
            int r0 = n0 + ty*8 + 2*j, r1 = r0 + 1;
            #pragma unroll
            for (int c = 0; c < 2; c++) {
                float a0, a1; upk(acc[j][c], a0, a1);
                if (r0 < NN) ob[(size_t)r0*COUT + lane + 32*c] = __float2bfloat16(a0*sc);
                if (r1 < NN) ob[(size_t)r1*COUT + lane + 32*c] = __float2bfloat16(a1*sc);
            }
        }
    } else {
        #pragma unroll
        for (int j = 0; j < 4; j++) {
            int r0 = n0 + ty*8 + 2*j, r1 = r0 + 1;
            #pragma unroll
            for (int c = 0; c < 2; c++) {
                float a0, a1; upk(acc[j][c], a0, a1);
                if (r0 < NN) g_s2[(size_t)r0*COUT + lane + 32*c] = a0;
                if (r1 < NN) g_s2[(size_t)r1*COUT + lane + 32*c] = a1;
            }
        }
    }
}

// ---------------- t tables (bf16 in/out) --------------------------------------
__global__ void k_t1(const float* __restrict__ We1) {
    int h = blockIdx.y;
    __shared__ float Wt[32][65];
    __shared__ float qsm[32][33];
    int tid = threadIdx.x;
    for (int i = tid; i < 64*32; i += 256) {
        int d = i >> 5, c = i & 31;
        Wt[c][d] = We1[(size_t)d*128 + h*32 + c];
    }
    int n0 = blockIdx.x * 32;
    for (int i = tid; i < 32*32; i += 256) {
        int nn = i >> 5, c = i & 31;
        qsm[nn][c] = (n0+nn < NN)
            ? __bfloat162float(g_q1b[(size_t)(n0+nn)*128 + h*32 + c]) : 0.f;
    }
    __syncthreads();
    int d = tid & 63, nb = tid >> 6;
    #pragma unroll
    for (int p = 0; p < 8; p++) {
        int nn = p*4 + nb;
        float acc = 0.f;
        #pragma unroll
        for (int c = 0; c < 32; c++) acc += qsm[nn][c] * Wt[c][d];
        if (n0+nn < NN) g_t1b[(size_t)(n0+nn)*256 + h*64 + d] = __float2bfloat16(acc);
    }
}

__global__ void k_t2(const float* __restrict__ We2) {
    __shared__ float Wt[64][65];
    __shared__ float qsm[32][65];
    int tid = threadIdx.x;
    for (int i = tid; i < 64*64; i += 256) {
        int d = i >> 6, c = i & 63;
        Wt[c][d] = We2[(size_t)d*64 + c];
    }
    int n0 = blockIdx.x * 32;
    for (int i = tid; i < 32*64; i += 256) {
        int nn = i >> 6, c = i & 63;
        qsm[nn][c] = (n0+nn < NN)
            ? __bfloat162float(g_q2b[(size_t)(n0+nn)*64 + c]) : 0.f;
    }
    __syncthreads();
    int d = tid & 63, nb = tid >> 6;
    #pragma unroll
    for (int p = 0; p < 8; p++) {
        int nn = p*4 + nb;
        float acc = 0.f;
        #pragma unroll
        for (int c = 0; c < 64; c++) acc += qsm[nn][c] * Wt[c][d];
        if (n0+nn < NN) g_t2b[(size_t)(n0+nn)*64 + d] = __float2bfloat16(acc);
    }
}

// ---------------- layer-1 scores + ef transcode -------------------------------
__global__ void __launch_bounds__(256) k_score1(const float* __restrict__ ef) {
    int tid  = threadIdx.x;
    int lane = tid & 31;
    int l8   = lane & 7;
    int i    = blockIdx.x*32 + (tid >> 3);   // EE % 32 == 0
    if (i >= EE) return;

    int2 se = g_edges[i];
    int  dn = g_edst[i];
    const uint2* kp = (const uint2*)(g_k1b + (size_t)se.x*128);
    const uint2* qp = (const uint2*)(g_q1b + (size_t)dn*128);
    const uint4* tp = (const uint4*)(g_t1b + (size_t)dn*256);
    const float4* ep = (const float4*)(ef + (size_t)se.y*64);

    float4 f0 = ldcs4f(ep + l8*2), f1 = ldcs4f(ep + l8*2 + 1);
    u32 e01 = f2bf2(f0.x, f0.y), e23 = f2bf2(f0.z, f0.w);
    u32 e45 = f2bf2(f1.x, f1.y), e67 = f2bf2(f1.z, f1.w);
    // transcode: store bf16 ef row in CSR-slot order (coalesced)
    stcs4u((u32*)(g_efb + (size_t)i*64) + l8*4, e01, e23, e45, e67);

    float s[4];
    #pragma unroll
    for (int h = 0; h < 4; h++) {
        uint2 kv = kp[h*8 + l8];
        uint2 qv = qp[h*8 + l8];
        u32 a = bffma2(kv.x, qv.x, 0u);
        a = bffma2(kv.y, qv.y, a);
        uint4 tv = tp[h*8 + l8];
        a = bffma2(e01, tv.x, a);
        a = bffma2(e23, tv.y, a);
        a = bffma2(e45, tv.z, a);
        a = bffma2(e67, tv.w, a);
        s[h] = bfsum2(a);
    }
    #pragma unroll
    for (int o = 1; o <= 4; o <<= 1) {
        s[0] += __shfl_xor_sync(FULL, s[0], o);
        s[1] += __shfl_xor_sync(FULL, s[1], o);
        s[2] += __shfl_xor_sync(FULL, s[2], o);
        s[3] += __shfl_xor_sync(FULL, s[3], o);
    }
    if (l8 == 0) {
        float4 w4;
        w4.x = __expf(s[0]); w4.y = __expf(s[1]);
        w4.z = __expf(s[2]); w4.w = __expf(s[3]);
        *(float4*)(g_w + (size_t)i*4) = w4;
    }
}

// ---------------- layer-1 aggregate (bf16 v + seq bf16 ef) --------------------
__global__ void __launch_bounds__(256) k_agg1(const float* __restrict__ We1) {
    int lane = threadIdx.x & 31;
    int wl   = threadIdx.x >> 5;
    int n    = blockIdx.x*8 + wl;
    __shared__ float smemAll[8*384];
    float* aux = smemAll + wl*384;
    float* gsm = aux + 128;
    if (n >= NN) return;

    int l8 = lane & 7, grp = lane >> 3;
    u64t accv0 = 0ull, accv1 = 0ull;
    u64t ag[4] = {0ull,0ull,0ull,0ull};
    float den = 0.f;

    int rs = g_rowptr[n], re = g_rowptr[n+1];
    for (int base = rs; base < re; base += 32) {
        int cnt = min(32, re - base);
        int srcl = 0;
        if (lane < cnt) {
            srcl = g_edges[base + lane].x;
            *(float4*)(aux + lane*4) = *(const float4*)(g_w + (size_t)(base+lane)*4);
        }
        __syncwarp();
        #pragma unroll 2
        for (int e = 0; e < cnt; e++) {
            int esrc = __shfl_sync(FULL, srcl, e);
            const float* we = aux + e*4;
            float w0 = we[0], w1 = we[1], w2 = we[2], w3 = we[3];
            float wg = (grp==0)?w0:((grp==1)?w1:((grp==2)?w2:w3));
            den += wg;
            u64t wgP = pk(wg, wg);
            uint2 vv = ((const uint2*)(g_v1b + (size_t)esrc*128))[lane];
            accv0 = f2fma(wgP, bf2f2(vv.x), accv0);
            accv1 = f2fma(wgP, bf2f2(vv.y), accv1);
            u32 ev = ldcs1u((const u32*)(g_efb + (size_t)(base+e)*64) + lane);
            u64t evF = bf2f2(ev);
            ag[0] = f2fma(pk(w0,w0), evF, ag[0]);
            ag[1] = f2fma(pk(w1,w1), evF, ag[1]);
            ag[2] = f2fma(pk(w2,w2), evF, ag[2]);
            ag[3] = f2fma(pk(w3,w3), evF, ag[3]);
        }
        __syncwarp();
    }

    u64t* gU = (u64t*)gsm;
    gU[0*32 + lane] = ag[0];
    gU[1*32 + lane] = ag[1];
    gU[2*32 + lane] = ag[2];
    gU[3*32 + lane] = ag[3];
    __syncwarp();

    float4 og = make_float4(0.f,0.f,0.f,0.f);
    const float* Wc = We1 + grp*32 + l8*4;
    const float* gh = gsm + grp*64;
    #pragma unroll 8
    for (int d = 0; d < 64; d++) {
        float g = gh[d];
        float4 wr = *(const float4*)(Wc + (size_t)d*128);
        og.x += g*wr.x; og.y += g*wr.y; og.z += g*wr.z; og.w += g*wr.w;
    }
    float inv = (den > 0.f) ? (1.f/den) : 0.f;
    float4 av; upk(accv0, av.x, av.y); upk(accv1, av.z, av.w);
    float4 skip = *(const float4*)(g_h + (size_t)n*128 + lane*4);
    float4 o;
    o.x = fmaxf(fmaf(av.x + og.x, inv, skip.x), 0.f);
    o.y = fmaxf(fmaf(av.y + og.y, inv, skip.y), 0.f);
    o.z = fmaxf(fmaf(av.z + og.z, inv, skip.z), 0.f);
    o.w = fmaxf(fmaf(av.w + og.w, inv, skip.w), 0.f);
    *(float4*)(g_h + (size_t)n*128 + lane*4) = o;
}

// ---------------- layer-2 scores (bf16, seq ef) --------------------------------
__global__ void __launch_bounds__(256) k_score2() {
    int tid  = threadIdx.x;
    int lane = tid & 31;
    int l8   = lane & 7;
    int i    = blockIdx.x*32 + (tid >> 3);
    if (i >= EE) return;

    int2 se = g_edges[i];
    int  dn = g_edst[i];
    const uint4* kp = (const uint4*)(g_k2b + (size_t)se.x*64);
    const uint4* qp = (const uint4*)(g_q2b + (size_t)dn*64);
    const uint4* tp = (const uint4*)(g_t2b + (size_t)dn*64);
    const uint4* ep = (const uint4*)(g_efb + (size_t)i*64);

    uint4 ev = ep[l8];          // sequential bf16 ef
    uint4 kv = kp[l8], qv = qp[l8], tv = tp[l8];
    u32 a = bffma2(kv.x, qv.x, 0u);
    a = bffma2(kv.y, qv.y, a);
    a = bffma2(kv.z, qv.z, a);
    a = bffma2(kv.w, qv.w, a);
    a = bffma2(ev.x, tv.x, a);
    a = bffma2(ev.y, tv.y, a);
    a = bffma2(ev.z, tv.z, a);
    a = bffma2(ev.w, tv.w, a);
    float s = bfsum2(a);
    s += __shfl_xor_sync(FULL, s, 1);
    s += __shfl_xor_sync(FULL, s, 2);
    s += __shfl_xor_sync(FULL, s, 4);
    if (l8 == 0) g_w[i] = __expf(s);
}

// ---------------- layer-2 aggregate (bf16 v + seq bf16 ef) ---------------------
__global__ void __launch_bounds__(256) k_agg2(const float* __restrict__ We2,
                                              float* __restrict__ out) {
    int lane = threadIdx.x & 31;
    int wl   = threadIdx.x >> 5;
    int n    = blockIdx.x*8 + wl;
    __shared__ float smemAll[8*96];
    float* aux = smemAll + wl*96;
    float* gsm = aux + 32;
    if (n >= NN) return;

    u64t accv = 0ull;
    u64t ag   = 0ull;
    float den = 0.f;
    int rs = g_rowptr[n], re = g_rowptr[n+1];

    for (int base = rs; base < re; base += 32) {
        int cnt = min(32, re - base);
        int srcl = 0;
        if (lane < cnt) {
            srcl = g_edges[base + lane].x;
            aux[lane] = g_w[base + lane];
        }
        __syncwarp();
        #pragma unroll 2
        for (int e = 0; e < cnt; e++) {
            int esrc = __shfl_sync(FULL, srcl, e);
            float w = aux[e];
            den += w;
            u64t wP = pk(w, w);
            u32 vv = ((const u32*)(g_v2b + (size_t)esrc*64))[lane];
            accv = f2fma(wP, bf2f2(vv), accv);
            u32 ev = ldcs1u((const u32*)(g_efb + (size_t)(base+e)*64) + lane);
            ag = f2fma(wP, bf2f2(ev), ag);
        }
        __syncwarp();
    }

    ((u64t*)gsm)[lane] = ag;
    __syncwarp();

    float2 og = make_float2(0.f,0.f);
    const float* Wc = We2 + lane*2;
    #pragma unroll 8
    for (int d = 0; d < 64; d++) {
        float g = gsm[d];
        float2 wr = *(const float2*)(Wc + (size_t)d*64);
        og.x += g*wr.x; og.y += g*wr.y;
    }
    float inv = (den > 0.f) ? (1.f/den) : 0.f;
    float2 av; upk(accv, av.x, av.y);
    float2 s2 = *(const float2*)(g_s2 + (size_t)n*64 + lane*2);
    float2 o;
    o.x = fmaf(av.x + og.x, inv, s2.x);
    o.y = fmaf(av.y + og.y, inv, s2.y);
    *(float2*)(out + (size_t)n*64 + lane*2) = o;
}

// ---------------- launch -------------------------------------------------------
extern "C" void kernel_launch(void* const* d_in, const int* in_sizes, int n_in,
                              void* d_out, int out_size)
{
    const float* x   = (const float*)d_in[0];
    const float* ef  = (const float*)d_in[1];
    const int*   ei  = (const int*)  d_in[2];
    const float *Wq1 = (const float*)d_in[3],  *bq1 = (const float*)d_in[4];
    const float *Wk1 = (const float*)d_in[5],  *bk1 = (const float*)d_in[6];
    const float *Wv1 = (const float*)d_in[7],  *bv1 = (const float*)d_in[8];
    const float *We1 = (const float*)d_in[9];
    const float *Ws1 = (const float*)d_in[10], *bs1 = (const float*)d_in[11];
    const float *Wq2 = (const float*)d_in[12], *bq2 = (const float*)d_in[13];
    const float *Wk2 = (const float*)d_in[14], *bk2 = (const float*)d_in[15];
    const float *Wv2 = (const float*)d_in[16], *bv2 = (const float*)d_in[17];
    const float *We2 = (const float*)d_in[18];
    const float *Ws2 = (const float*)d_in[19], *bs2 = (const float*)d_in[20];
    float* out = (float*)d_out;

    const int* srcp = ei;
    const int* dstp = ei + EE;

    // CSR build
    k_zero_cnt<<<(NN+255)/256, 256>>>();
    k_hist    <<<(EE+255)/256, 256>>>(dstp);
    k_scanA   <<<49, 1024>>>();
    k_scanB   <<<1, 64>>>();
    k_scanC   <<<(NN+255)/256, 256>>>();
    k_scatter <<<(EE+255)/256, 256>>>(srcp, dstp);

    // layer 1
    dim3 g1((NN+63)/64, 4);
    k_node1 <<<g1, 256>>>(x, Wq1,bq1, Wk1,bk1, Wv1,bv1, Ws1,bs1);
    dim3 gt1((NN+31)/32, 4);
    k_t1    <<<gt1, 256>>>(We1);
    k_score1<<<EE/32, 256>>>(ef);
    k_agg1  <<<(NN+7)/8, 256>>>(We1);

    // layer 2
    dim3 g2((NN+63)/64, 4);
    k_node2 <<<g2, 256>>>(Wq2,bq2, Wk2,bk2, Wv2,bv2, Ws2,bs2);
    k_t2    <<<(NN+31)/32, 256>>>(We2);
    k_score2<<<EE/32, 256>>>();
    k_agg2  <<<(NN+7)/8, 256>>>(We2, out);
}

// round 16
// speedup vs baseline: 1.0467x; 1.0467x over previous
#include <cuda_runtime.h>
#include <cuda_bf16.h>

#define NN 50000
#define EE 1600000
#define FULL 0xffffffffu

typedef unsigned long long u64t;
typedef unsigned int u32;

__device__ __forceinline__ u64t pk(float lo, float hi) {
    u64t r; asm("mov.b64 %0,{%1,%2};" : "=l"(r) : "f"(lo), "f"(hi)); return r;
}
__device__ __forceinline__ void upk(u64t v, float& lo, float& hi) {
    asm("mov.b64 {%0,%1},%2;" : "=f"(lo), "=f"(hi) : "l"(v));
}
__device__ __forceinline__ u64t f2fma(u64t a, u64t b, u64t c) {
    u64t d; asm("fma.rn.f32x2 %0,%1,%2,%3;" : "=l"(d) : "l"(a), "l"(b), "l"(c)); return d;
}
__device__ __forceinline__ u64t ldcs1(const u64t* p) {
    u64t r; asm("ld.global.cs.u64 %0,[%1];" : "=l"(r) : "l"(p)); return r;
}
__device__ __forceinline__ float4 ldcs4f(const float4* p) {
    float4 r;
    asm("ld.global.cs.v4.f32 {%0,%1,%2,%3},[%4];"
        : "=f"(r.x), "=f"(r.y), "=f"(r.z), "=f"(r.w) : "l"(p));
    return r;
}
__device__ __forceinline__ u32 bffma2(u32 a, u32 b, u32 c) {
    u32 d; asm("fma.rn.bf16x2 %0,%1,%2,%3;" : "=r"(d) : "r"(a), "r"(b), "r"(c)); return d;
}
__device__ __forceinline__ float bfsum2(u32 v) {
    float lo = __uint_as_float(v << 16);
    float hi = __uint_as_float(v & 0xffff0000u);
    return lo + hi;
}
__device__ __forceinline__ u32 f2bf2(float lo, float hi) {
    u32 r; asm("cvt.rn.bf16x2.f32 %0,%1,%2;" : "=r"(r) : "f"(hi), "f"(lo)); return r;
}

// ---------------- scratch ----------------------------------------------------
__device__ __nv_bfloat16 g_q1b[NN*128];   // pre-scaled by 1/sqrt(32)
__device__ __nv_bfloat16 g_k1b[NN*128];
__device__ __nv_bfloat16 g_t1b[NN*256];
__device__ __nv_bfloat16 g_q2b[NN*64];    // pre-scaled by 0.125
__device__ __nv_bfloat16 g_k2b[NN*64];
__device__ __nv_bfloat16 g_t2b[NN*64];
__device__ float g_v1[NN*128];
__device__ float g_h [NN*128];
__device__ float g_v2[NN*64];
__device__ float g_s2[NN*64];
__device__ float g_w [EE*4];
__device__ int   g_cnt[NN];
__device__ int   g_rowptr[NN+1];
__device__ int   g_woff[NN];
__device__ int   g_bsum[64];
__device__ int2  g_edges[EE];
__device__ int   g_edst[EE];

// ---------------- CSR build ---------------------------------------------------
__global__ void k_zero_cnt() {
    int i = blockIdx.x*blockDim.x + threadIdx.x;
    if (i < NN) g_cnt[i] = 0;
}
__global__ void k_hist(const int* __restrict__ dst) {
    int e = blockIdx.x*blockDim.x + threadIdx.x;
    if (e < EE) atomicAdd(&g_cnt[dst[e]], 1);
}
__global__ void k_scanA() {
    __shared__ int s[1024];
    int b = blockIdx.x;
    int i = b*1024 + threadIdx.x;
    int v = (i < NN) ? g_cnt[i] : 0;
    s[threadIdx.x] = v;
    __syncthreads();
    for (int off = 1; off < 1024; off <<= 1) {
        int t = (threadIdx.x >= off) ? s[threadIdx.x - off] : 0;
        __syncthreads();
        s[threadIdx.x] += t;
        __syncthreads();
    }
    if (i < NN) g_rowptr[i] = s[threadIdx.x] - v;
    if (threadIdx.x == 1023) g_bsum[b] = s[1023];
}
__global__ void k_scanB() {
    __shared__ int s[64];
    int t = threadIdx.x;
    int v = (t < 49) ? g_bsum[t] : 0;
    s[t] = v;
    __syncthreads();
    for (int off = 1; off < 64; off <<= 1) {
        int x = (t >= off) ? s[t - off] : 0;
        __syncthreads();
        s[t] += x;
        __syncthreads();
    }
    if (t < 49) g_bsum[t] = s[t] - v;
    if (t == 48) g_rowptr[NN] = s[48];
}
__global__ void k_scanC() {
    int i = blockIdx.x*blockDim.x + threadIdx.x;
    if (i < NN) {
        int r = g_rowptr[i] + g_bsum[i >> 10];
        g_rowptr[i] = r;
        g_woff[i] = r;
    }
}
__global__ void k_scatter(const int* __restrict__ src, const int* __restrict__ dst) {
    int e = blockIdx.x*blockDim.x + threadIdx.x;
    if (e < EE) {
        int d = dst[e];
        int p = atomicAdd(&g_woff[d], 1);
        g_edges[p] = make_int2(src[e], e);
        g_edst[p] = d;
    }
}

// ---------------- node linear layer 1 (R4 measured-good; bf16 epilogue) ------
__global__ void k_node1(const float* __restrict__ x,
    const float* __restrict__ Wq, const float* __restrict__ bq,
    const float* __restrict__ Wk, const float* __restrict__ bk,
    const float* __restrict__ Wv, const float* __restrict__ bv,
    const float* __restrict__ Ws, const float* __restrict__ bs)
{
    const int CIN = 128, COUT = 128, BN = 16;
    int mat = blockIdx.y;
    const float* W = (mat==0)?Wq:((mat==1)?Wk:((mat==2)?Wv:Ws));
    const float* b = (mat==0)?bq:((mat==1)?bk:((mat==2)?bv:bs));
    int n0 = blockIdx.x * BN;

    __shared__ float xs[CIN][BN];
    for (int i = threadIdx.x; i < BN*CIN; i += COUT) {
        int nn = i / CIN, c = i % CIN;
        xs[c][nn] = x[(size_t)(n0+nn)*CIN + c];
    }
    __syncthreads();

    int col = threadIdx.x;
    float bb = b[col];
    u64t accP[8];
    u64t bbP = pk(bb, bb);
    #pragma unroll
    for (int j = 0; j < 8; j++) accP[j] = bbP;

    #pragma unroll 2
    for (int k = 0; k < CIN; k++) {
        float wv = W[(size_t)k*COUT + col];
        u64t wvP = pk(wv, wv);
        const u64t* xr = (const u64t*)xs[k];
        #pragma unroll
        for (int j = 0; j < 8; j++) accP[j] = f2fma(wvP, xr[j], accP[j]);
    }
    if (mat < 2) {
        __nv_bfloat16* ob = (mat==0) ? g_q1b : g_k1b;
        float sc = (mat==0) ? 0.1767766952966369f : 1.f;
        #pragma unroll
        for (int j = 0; j < 8; j++) {
            float a0, a1; upk(accP[j], a0, a1);
            ob[(size_t)(n0+2*j)*COUT + col]   = __float2bfloat16(a0*sc);
            ob[(size_t)(n0+2*j+1)*COUT + col] = __float2bfloat16(a1*sc);
        }
    } else {
        float* o = (mat==2) ? g_v1 : g_h;
        #pragma unroll
        for (int j = 0; j < 8; j++) {
            float a0, a1; upk(accP[j], a0, a1);
            o[(size_t)(n0+2*j)*COUT + col]   = a0;
            o[(size_t)(n0+2*j+1)*COUT + col] = a1;
        }
    }
}

__global__ void k_node2(
    const float* __restrict__ Wq, const float* __restrict__ bq,
    const float* __restrict__ Wk, const float* __restrict__ bk,
    const float* __restrict__ Wv, const float* __restrict__ bv,
    const float* __restrict__ Ws, const float* __restrict__ bs)
{
    const int CIN = 128, COUT = 64, BN = 16;
    int mat = blockIdx.y;
    const float* W = (mat==0)?Wq:((mat==1)?Wk:((mat==2)?Wv:Ws));
    const float* b = (mat==0)?bq:((mat==1)?bk:((mat==2)?bv:bs));
    int n0 = blockIdx.x * BN;

    __shared__ float xs[CIN][BN];
    for (int i = threadIdx.x; i < BN*CIN; i += COUT) {
        int nn = i / CIN, c = i % CIN;
        xs[c][nn] = g_h[(size_t)(n0+nn)*CIN + c];
    }
    __syncthreads();

    int col = threadIdx.x;
    float bb = b[col];
    u64t accP[8];
    u64t bbP = pk(bb, bb);
    #pragma unroll
    for (int j = 0; j < 8; j++) accP[j] = bbP;

    #pragma unroll 2
    for (int k = 0; k < CIN; k++) {
        float wv = W[(size_t)k*COUT + col];
        u64t wvP = pk(wv, wv);
        const u64t* xr = (const u64t*)xs[k];
        #pragma unroll
        for (int j = 0; j < 8; j++) accP[j] = f2fma(wvP, xr[j], accP[j]);
    }
    if (mat < 2) {
        __nv_bfloat16* ob = (mat==0) ? g_q2b : g_k2b;
        float sc = (mat==0) ? 0.125f : 1.f;
        #pragma unroll
        for (int j = 0; j < 8; j++) {
            float a0, a1; upk(accP[j], a0, a1);
            ob[(size_t)(n0+2*j)*COUT + col]   = __float2bfloat16(a0*sc);
            ob[(size_t)(n0+2*j+1)*COUT + col] = __float2bfloat16(a1*sc);
        }
    } else {
        float* o = (mat==2) ? g_v2 : g_s2;
        #pragma unroll
        for (int j = 0; j < 8; j++) {
            float a0, a1; upk(accP[j], a0, a1);
            o[(size_t)(n0+2*j)*COUT + col]   = a0;
            o[(size_t)(n0+2*j+1)*COUT + col] = a1;
        }
    }
}

// ---------------- t tables (bf16 in/out) --------------------------------------
__global__ void k_t1(const float* __restrict__ We1) {
    int h = blockIdx.y;
    __shared__ float Wt[32][65];
    __shared__ float qsm[32][33];
    int tid = threadIdx.x;
    for (int i = tid; i < 64*32; i += 256) {
        int d = i >> 5, c = i & 31;
        Wt[c][d] = We1[(size_t)d*128 + h*32 + c];
    }
    int n0 = blockIdx.x * 32;
    for (int i = tid; i < 32*32; i += 256) {
        int nn = i >> 5, c = i & 31;
        qsm[nn][c] = (n0+nn < NN)
            ? __bfloat162float(g_q1b[(size_t)(n0+nn)*128 + h*32 + c]) : 0.f;
    }
    __syncthreads();
    int d = tid & 63, nb = tid >> 6;
    #pragma unroll
    for (int p = 0; p < 8; p++) {
        int nn = p*4 + nb;
        float acc = 0.f;
        #pragma unroll
        for (int c = 0; c < 32; c++) acc += qsm[nn][c] * Wt[c][d];
        if (n0+nn < NN) g_t1b[(size_t)(n0+nn)*256 + h*64 + d] = __float2bfloat16(acc);
    }
}

__global__ void k_t2(const float* __restrict__ We2) {
    __shared__ float Wt[64][65];
    __shared__ float qsm[32][65];
    int tid = threadIdx.x;
    for (int i = tid; i < 64*64; i += 256) {
        int d = i >> 6, c = i & 63;
        Wt[c][d] = We2[(size_t)d*64 + c];
    }
    int n0 = blockIdx.x * 32;
    for (int i = tid; i < 32*64; i += 256) {
        int nn = i >> 6, c = i & 63;
        qsm[nn][c] = (n0+nn < NN)
            ? __bfloat162float(g_q2b[(size_t)(n0+nn)*64 + c]) : 0.f;
    }
    __syncthreads();
    int d = tid & 63, nb = tid >> 6;
    #pragma unroll
    for (int p = 0; p < 8; p++) {
        int nn = p*4 + nb;
        float acc = 0.f;
        #pragma unroll
        for (int c = 0; c < 64; c++) acc += qsm[nn][c] * Wt[c][d];
        if (n0+nn < NN) g_t2b[(size_t)(n0+nn)*64 + d] = __float2bfloat16(acc);
    }
}

// ---------------- layer-1 scores: edge-parallel, bf16 dot --------------------
__global__ void __launch_bounds__(256) k_score1(const float* __restrict__ ef) {
    int tid  = threadIdx.x;
    int lane = tid & 31;
    int l8   = lane & 7;
    int i    = blockIdx.x*32 + (tid >> 3);   // EE % 32 == 0
    if (i >= EE) return;

    int2 se = g_edges[i];
    int  dn = g_edst[i];
    const uint2* kp = (const uint2*)(g_k1b + (size_t)se.x*128);
    const uint2* qp = (const uint2*)(g_q1b + (size_t)dn*128);
    const uint4* tp = (const uint4*)(g_t1b + (size_t)dn*256);
    const float4* ep = (const float4*)(ef + (size_t)se.y*64);

    float4 f0 = ldcs4f(ep + l8*2), f1 = ldcs4f(ep + l8*2 + 1);
    u32 e01 = f2bf2(f0.x, f0.y), e23 = f2bf2(f0.z, f0.w);
    u32 e45 = f2bf2(f1.x, f1.y), e67 = f2bf2(f1.z, f1.w);

    float s[4];
    #pragma unroll
    for (int h = 0; h < 4; h++) {
        uint2 kv = kp[h*8 + l8];
        uint2 qv = qp[h*8 + l8];
        u32 a = bffma2(kv.x, qv.x, 0u);
        a = bffma2(kv.y, qv.y, a);
        uint4 tv = tp[h*8 + l8];
        a = bffma2(e01, tv.x, a);
        a = bffma2(e23, tv.y, a);
        a = bffma2(e45, tv.z, a);
        a = bffma2(e67, tv.w, a);
        s[h] = bfsum2(a);
    }
    #pragma unroll
    for (int o = 1; o <= 4; o <<= 1) {
        s[0] += __shfl_xor_sync(FULL, s[0], o);
        s[1] += __shfl_xor_sync(FULL, s[1], o);
        s[2] += __shfl_xor_sync(FULL, s[2], o);
        s[3] += __shfl_xor_sync(FULL, s[3], o);
    }
    if (l8 == 0) {
        float4 w4;
        w4.x = __expf(s[0]); w4.y = __expf(s[1]);
        w4.z = __expf(s[2]); w4.w = __expf(s[3]);
        *(float4*)(g_w + (size_t)i*4) = w4;
    }
}

// ---------------- layer-1 aggregate (fp32, R8) ---------------------------------
__global__ void __launch_bounds__(256) k_agg1(const float* __restrict__ ef,
                                              const float* __restrict__ We1) {
    int lane = threadIdx.x & 31;
    int wl   = threadIdx.x >> 5;
    int n    = blockIdx.x*8 + wl;
    __shared__ float smemAll[8*384];
    float* aux = smemAll + wl*384;
    float* gsm = aux + 128;
    if (n >= NN) return;

    int l8 = lane & 7, grp = lane >> 3;
    u64t accv0 = 0ull, accv1 = 0ull;
    u64t ag[4] = {0ull,0ull,0ull,0ull};
    float den = 0.f;

    int rs = g_rowptr[n], re = g_rowptr[n+1];
    for (int base = rs; base < re; base += 32) {
        int cnt = min(32, re - base);
        int2 se = make_int2(0, 0);
        if (lane < cnt) {
            se = g_edges[base + lane];
            *(float4*)(aux + lane*4) = *(const float4*)(g_w + (size_t)(base+lane)*4);
        }
        __syncwarp();
        #pragma unroll 2
        for (int e = 0; e < cnt; e++) {
            int esrc = __shfl_sync(FULL, se.x, e);
            int eeid = __shfl_sync(FULL, se.y, e);
            const float* we = aux + e*4;
            float w0 = we[0], w1 = we[1], w2 = we[2], w3 = we[3];
            float wg = (grp==0)?w0:((grp==1)?w1:((grp==2)?w2:w3));
            den += wg;
            u64t wgP = pk(wg, wg);
            ulonglong2 vv = ((const ulonglong2*)(g_v1 + (size_t)esrc*128))[lane];
            accv0 = f2fma(wgP, vv.x, accv0);
            accv1 = f2fma(wgP, vv.y, accv1);
            u64t ev = ldcs1((const u64t*)(ef + (size_t)eeid*64) + lane);
            ag[0] = f2fma(pk(w0,w0), ev, ag[0]);
            ag[1] = f2fma(pk(w1,w1), ev, ag[1]);
            ag[2] = f2fma(pk(w2,w2), ev, ag[2]);
            ag[3] = f2fma(pk(w3,w3), ev, ag[3]);
        }
        __syncwarp();
    }

    u64t* gU = (u64t*)gsm;
    gU[0*32 + lane] = ag[0];
    gU[1*32 + lane] = ag[1];
    gU[2*32 + lane] = ag[2];
    gU[3*32 + lane] = ag[3];
    __syncwarp();

    float4 og = make_float4(0.f,0.f,0.f,0.f);
    const float* Wc = We1 + grp*32 + l8*4;
    const float* gh = gsm + grp*64;
    #pragma unroll 8
    for (int d = 0; d < 64; d++) {
        float g = gh[d];
        float4 wr = *(const float4*)(Wc + (size_t)d*128);
        og.x += g*wr.x; og.y += g*wr.y; og.z += g*wr.z; og.w += g*wr.w;
    }
    float inv = (den > 0.f) ? (1.f/den) : 0.f;
    float4 av; upk(accv0, av.x, av.y); upk(accv1, av.z, av.w);
    float4 skip = *(const float4*)(g_h + (size_t)n*128 + lane*4);
    float4 o;
    o.x = fmaxf(fmaf(av.x + og.x, inv, skip.x), 0.f);
    o.y = fmaxf(fmaf(av.y + og.y, inv, skip.y), 0.f);
    o.z = fmaxf(fmaf(av.z + og.z, inv, skip.z), 0.f);
    o.w = fmaxf(fmaf(av.w + og.w, inv, skip.w), 0.f);
    *(float4*)(g_h + (size_t)n*128 + lane*4) = o;
}

// ---------------- layer-2 scores: edge-parallel, bf16 dot ---------------------
__global__ void __launch_bounds__(256) k_score2(const float* __restrict__ ef) {
    int tid  = threadIdx.x;
    int lane = tid & 31;
    int l8   = lane & 7;
    int i    = blockIdx.x*32 + (tid >> 3);
    if (i >= EE) return;

    int2 se = g_edges[i];
    int  dn = g_edst[i];
    const uint4* kp = (const uint4*)(g_k2b + (size_t)se.x*64);
    const uint4* qp = (const uint4*)(g_q2b + (size_t)dn*64);
    const uint4* tp = (const uint4*)(g_t2b + (size_t)dn*64);
    const float4* ep = (const float4*)(ef + (size_t)se.y*64);

    float4 f0 = ldcs4f(ep + l8*2), f1 = ldcs4f(ep + l8*2 + 1);
    u32 e01 = f2bf2(f0.x, f0.y), e23 = f2bf2(f0.z, f0.w);
    u32 e45 = f2bf2(f1.x, f1.y), e67 = f2bf2(f1.z, f1.w);

    uint4 kv = kp[l8], qv = qp[l8], tv = tp[l8];
    u32 a = bffma2(kv.x, qv.x, 0u);
    a = bffma2(kv.y, qv.y, a);
    a = bffma2(kv.z, qv.z, a);
    a = bffma2(kv.w, qv.w, a);
    a = bffma2(e01, tv.x, a);
    a = bffma2(e23, tv.y, a);
    a = bffma2(e45, tv.z, a);
    a = bffma2(e67, tv.w, a);
    float s = bfsum2(a);
    s += __shfl_xor_sync(FULL, s, 1);
    s += __shfl_xor_sync(FULL, s, 2);
    s += __shfl_xor_sync(FULL, s, 4);
    if (l8 == 0) g_w[i] = __expf(s);
}

// ---------------- layer-2 aggregate (fp32, R8) ----------------------------------
__global__ void __launch_bounds__(256) k_agg2(const float* __restrict__ ef,
                                              const float* __restrict__ We2,
                                              float* __restrict__ out) {
    int lane = threadIdx.x & 31;
    int wl   = threadIdx.x >> 5;
    int n    = blockIdx.x*8 + wl;
    __shared__ float smemAll[8*96];
    float* aux = smemAll + wl*96;
    float* gsm = aux + 32;
    if (n >= NN) return;

    u64t accv = 0ull;
    u64t ag   = 0ull;
    float den = 0.f;
    int rs = g_rowptr[n], re = g_rowptr[n+1];

    for (int base = rs; base < re; base += 32) {
        int cnt = min(32, re - base);
        int2 se = make_int2(0, 0);
        if (lane < cnt) {
            se = g_edges[base + lane];
            aux[lane] = g_w[base + lane];
        }
        __syncwarp();
        #pragma unroll 2
        for (int e = 0; e < cnt; e++) {
            int esrc = __shfl_sync(FULL, se.x, e);
            int eeid = __shfl_sync(FULL, se.y, e);
            float w = aux[e];
            den += w;
            u64t wP = pk(w, w);
            u64t vv = ((const u64t*)(g_v2 + (size_t)esrc*64))[lane];
            accv = f2fma(wP, vv, accv);
            u64t ev = ldcs1((const u64t*)(ef + (size_t)eeid*64) + lane);
            ag = f2fma(wP, ev, ag);
        }
        __syncwarp();
    }

    ((u64t*)gsm)[lane] = ag;
    __syncwarp();

    float2 og = make_float2(0.f,0.f);
    const float* Wc = We2 + lane*2;
    #pragma unroll 8
    for (int d = 0; d < 64; d++) {
        float g = gsm[d];
        float2 wr = *(const float2*)(Wc + (size_t)d*64);
        og.x += g*wr.x; og.y += g*wr.y;
    }
    float inv = (den > 0.f) ? (1.f/den) : 0.f;
    float2 av; upk(accv, av.x, av.y);
    float2 s2 = *(const float2*)(g_s2 + (size_t)n*64 + lane*2);
    float2 o;
    o.x = fmaf(av.x + og.x, inv, s2.x);
    o.y = fmaf(av.y + og.y, inv, s2.y);
    *(float2*)(out + (size_t)n*64 + lane*2) = o;
}

// ---------------- launch -------------------------------------------------------
extern "C" void kernel_launch(void* const* d_in, const int* in_sizes, int n_in,
                              void* d_out, int out_size)
{
    const float* x   = (const float*)d_in[0];
    const float* ef  = (const float*)d_in[1];
    const int*   ei  = (const int*)  d_in[2];
    const float *Wq1 = (const float*)d_in[3],  *bq1 = (const float*)d_in[4];
    const float *Wk1 = (const float*)d_in[5],  *bk1 = (const float*)d_in[6];
    const float *Wv1 = (const float*)d_in[7],  *bv1 = (const float*)d_in[8];
    const float *We1 = (const float*)d_in[9];
    const float *Ws1 = (const float*)d_in[10], *bs1 = (const float*)d_in[11];
    const float *Wq2 = (const float*)d_in[12], *bq2 = (const float*)d_in[13];
    const float *Wk2 = (const float*)d_in[14], *bk2 = (const float*)d_in[15];
    const float *Wv2 = (const float*)d_in[16], *bv2 = (const float*)d_in[17];
    const float *We2 = (const float*)d_in[18];
    const float *Ws2 = (const float*)d_in[19], *bs2 = (const float*)d_in[20];
    float* out = (float*)d_out;

    const int* srcp = ei;
    const int* dstp = ei + EE;

    // CSR build
    k_zero_cnt<<<(NN+255)/256, 256>>>();
    k_hist    <<<(EE+255)/256, 256>>>(dstp);
    k_scanA   <<<49, 1024>>>();
    k_scanB   <<<1, 64>>>();
    k_scanC   <<<(NN+255)/256, 256>>>();
    k_scatter <<<(EE+255)/256, 256>>>(srcp, dstp);

    // layer 1
    dim3 g1(NN/16, 4);
    k_node1 <<<g1, 128>>>(x, Wq1,bq1, Wk1,bk1, Wv1,bv1, Ws1,bs1);
    dim3 gt1((NN+31)/32, 4);
    k_t1    <<<gt1, 256>>>(We1);
    k_score1<<<EE/32, 256>>>(ef);
    k_agg1  <<<(NN+7)/8, 256>>>(ef, We1);

    // layer 2
    k_node2 <<<g1, 64>>>(Wq2,bq2, Wk2,bk2, Wv2,bv2, Ws2,bs2);
    k_t2    <<<(NN+31)/32, 256>>>(We2);
    k_score2<<<EE/32, 256>>>(ef);
    k_agg2  <<<(NN+7)/8, 256>>>(ef, We2, out);
}

// round 17
// speedup vs baseline: 1.0792x; 1.0310x over previous
#include <cuda_runtime.h>
#include <cuda_bf16.h>

#define NN 50000
#define EE 1600000
#define FULL 0xffffffffu

typedef unsigned long long u64t;
typedef unsigned int u32;

__device__ __forceinline__ u64t pk(float lo, float hi) {
    u64t r; asm("mov.b64 %0,{%1,%2};" : "=l"(r) : "f"(lo), "f"(hi)); return r;
}
__device__ __forceinline__ void upk(u64t v, float& lo, float& hi) {
    asm("mov.b64 {%0,%1},%2;" : "=f"(lo), "=f"(hi) : "l"(v));
}
__device__ __forceinline__ u64t f2fma(u64t a, u64t b, u64t c) {
    u64t d; asm("fma.rn.f32x2 %0,%1,%2,%3;" : "=l"(d) : "l"(a), "l"(b), "l"(c)); return d;
}
__device__ __forceinline__ u64t ldcs1(const u64t* p) {
    u64t r; asm("ld.global.cs.u64 %0,[%1];" : "=l"(r) : "l"(p)); return r;
}
__device__ __forceinline__ float4 ldcs4f(const float4* p) {
    float4 r;
    asm("ld.global.cs.v4.f32 {%0,%1,%2,%3},[%4];"
        : "=f"(r.x), "=f"(r.y), "=f"(r.z), "=f"(r.w) : "l"(p));
    return r;
}
__device__ __forceinline__ u32 bffma2(u32 a, u32 b, u32 c) {
    u32 d; asm("fma.rn.bf16x2 %0,%1,%2,%3;" : "=r"(d) : "r"(a), "r"(b), "r"(c)); return d;
}
__device__ __forceinline__ float bfsum2(u32 v) {
    float lo = __uint_as_float(v << 16);
    float hi = __uint_as_float(v & 0xffff0000u);
    return lo + hi;
}
__device__ __forceinline__ u32 f2bf2(float lo, float hi) {
    u32 r; asm("cvt.rn.bf16x2.f32 %0,%1,%2;" : "=r"(r) : "f"(hi), "f"(lo)); return r;
}

// ---------------- scratch ----------------------------------------------------
__device__ __nv_bfloat16 g_q1b[NN*128];   // pre-scaled by 1/sqrt(32)
__device__ __nv_bfloat16 g_k1b[NN*128];
__device__ __nv_bfloat16 g_t1b[NN*256];
__device__ __nv_bfloat16 g_q2b[NN*64];    // pre-scaled by 0.125
__device__ __nv_bfloat16 g_k2b[NN*64];
__device__ __nv_bfloat16 g_t2b[NN*64];
__device__ float g_v1[NN*128];
__device__ float g_h [NN*128];
__device__ float g_v2[NN*64];
__device__ float g_s2[NN*64];
__device__ float g_w [EE*4];
__device__ int   g_cnt[NN];
__device__ int   g_rowptr[NN+1];
__device__ int   g_woff[NN];
__device__ int   g_bsum[64];
__device__ int2  g_edges[EE];
__device__ int   g_edst[EE];

// ---------------- CSR build ---------------------------------------------------
__global__ void k_zero_cnt() {
    int i = blockIdx.x*blockDim.x + threadIdx.x;
    if (i < NN) g_cnt[i] = 0;
}
__global__ void k_hist(const int* __restrict__ dst) {
    int e = blockIdx.x*blockDim.x + threadIdx.x;
    if (e < EE) atomicAdd(&g_cnt[dst[e]], 1);
}
__global__ void k_scanA() {
    __shared__ int s[1024];
    int b = blockIdx.x;
    int i = b*1024 + threadIdx.x;
    int v = (i < NN) ? g_cnt[i] : 0;
    s[threadIdx.x] = v;
    __syncthreads();
    for (int off = 1; off < 1024; off <<= 1) {
        int t = (threadIdx.x >= off) ? s[threadIdx.x - off] : 0;
        __syncthreads();
        s[threadIdx.x] += t;
        __syncthreads();
    }
    if (i < NN) g_rowptr[i] = s[threadIdx.x] - v;
    if (threadIdx.x == 1023) g_bsum[b] = s[1023];
}
__global__ void k_scanB() {
    __shared__ int s[64];
    int t = threadIdx.x;
    int v = (t < 49) ? g_bsum[t] : 0;
    s[t] = v;
    __syncthreads();
    for (int off = 1; off < 64; off <<= 1) {
        int x = (t >= off) ? s[t - off] : 0;
        __syncthreads();
        s[t] += x;
        __syncthreads();
    }
    if (t < 49) g_bsum[t] = s[t] - v;
    if (t == 48) g_rowptr[NN] = s[48];
}
__global__ void k_scanC() {
    int i = blockIdx.x*blockDim.x + threadIdx.x;
    if (i < NN) {
        int r = g_rowptr[i] + g_bsum[i >> 10];
        g_rowptr[i] = r;
        g_woff[i] = r;
    }
}
__global__ void k_scatter(const int* __restrict__ src, const int* __restrict__ dst) {
    int e = blockIdx.x*blockDim.x + threadIdx.x;
    if (e < EE) {
        int d = dst[e];
        int p = atomicAdd(&g_woff[d], 1);
        g_edges[p] = make_int2(src[e], e);
        g_edst[p] = d;
    }
}

// ---------------- node linear layer 1 (R4 + pad-20 + LDS.128) ----------------
__global__ void k_node1(const float* __restrict__ x,
    const float* __restrict__ Wq, const float* __restrict__ bq,
    const float* __restrict__ Wk, const float* __restrict__ bk,
    const float* __restrict__ Wv, const float* __restrict__ bv,
    const float* __restrict__ Ws, const float* __restrict__ bs)
{
    const int CIN = 128, COUT = 128, BN = 16;
    int mat = blockIdx.y;
    const float* W = (mat==0)?Wq:((mat==1)?Wk:((mat==2)?Wv:Ws));
    const float* b = (mat==0)?bq:((mat==1)?bk:((mat==2)?bv:bs));
    int n0 = blockIdx.x * BN;

    __shared__ float xs[CIN][BN+4];   // 80B rows: 16B-aligned, 4-way STS conflicts
    for (int i = threadIdx.x; i < BN*CIN; i += COUT) {
        int nn = i / CIN, c = i % CIN;
        xs[c][nn] = x[(size_t)(n0+nn)*CIN + c];
    }
    __syncthreads();

    int col = threadIdx.x;
    float bb = b[col];
    u64t accP[8];
    u64t bbP = pk(bb, bb);
    #pragma unroll
    for (int j = 0; j < 8; j++) accP[j] = bbP;

    #pragma unroll 2
    for (int k = 0; k < CIN; k++) {
        float wv = W[(size_t)k*COUT + col];
        u64t wvP = pk(wv, wv);
        const ulonglong2* xr = (const ulonglong2*)xs[k];
        ulonglong2 p0 = xr[0], p1 = xr[1], p2 = xr[2], p3 = xr[3];
        accP[0] = f2fma(wvP, p0.x, accP[0]); accP[1] = f2fma(wvP, p0.y, accP[1]);
        accP[2] = f2fma(wvP, p1.x, accP[2]); accP[3] = f2fma(wvP, p1.y, accP[3]);
        accP[4] = f2fma(wvP, p2.x, accP[4]); accP[5] = f2fma(wvP, p2.y, accP[5]);
        accP[6] = f2fma(wvP, p3.x, accP[6]); accP[7] = f2fma(wvP, p3.y, accP[7]);
    }
    if (mat < 2) {
        __nv_bfloat16* ob = (mat==0) ? g_q1b : g_k1b;
        float sc = (mat==0) ? 0.1767766952966369f : 1.f;
        #pragma unroll
        for (int j = 0; j < 8; j++) {
            float a0, a1; upk(accP[j], a0, a1);
            ob[(size_t)(n0+2*j)*COUT + col]   = __float2bfloat16(a0*sc);
            ob[(size_t)(n0+2*j+1)*COUT + col] = __float2bfloat16(a1*sc);
        }
    } else {
        float* o = (mat==2) ? g_v1 : g_h;
        #pragma unroll
        for (int j = 0; j < 8; j++) {
            float a0, a1; upk(accP[j], a0, a1);
            o[(size_t)(n0+2*j)*COUT + col]   = a0;
            o[(size_t)(n0+2*j+1)*COUT + col] = a1;
        }
    }
}

__global__ void k_node2(
    const float* __restrict__ Wq, const float* __restrict__ bq,
    const float* __restrict__ Wk, const float* __restrict__ bk,
    const float* __restrict__ Wv, const float* __restrict__ bv,
    const float* __restrict__ Ws, const float* __restrict__ bs)
{
    const int CIN = 128, COUT = 64, BN = 16;
    int mat = blockIdx.y;
    const float* W = (mat==0)?Wq:((mat==1)?Wk:((mat==2)?Wv:Ws));
    const float* b = (mat==0)?bq:((mat==1)?bk:((mat==2)?bv:bs));
    int n0 = blockIdx.x * BN;

    __shared__ float xs[CIN][BN+4];
    for (int i = threadIdx.x; i < BN*CIN; i += COUT) {
        int nn = i / CIN, c = i % CIN;
        xs[c][nn] = g_h[(size_t)(n0+nn)*CIN + c];
    }
    __syncthreads();

    int col = threadIdx.x;
    float bb = b[col];
    u64t accP[8];
    u64t bbP = pk(bb, bb);
    #pragma unroll
    for (int j = 0; j < 8; j++) accP[j] = bbP;

    #pragma unroll 2
    for (int k = 0; k < CIN; k++) {
        float wv = W[(size_t)k*COUT + col];
        u64t wvP = pk(wv, wv);
        const ulonglong2* xr = (const ulonglong2*)xs[k];
        ulonglong2 p0 = xr[0], p1 = xr[1], p2 = xr[2], p3 = xr[3];
        accP[0] = f2fma(wvP, p0.x, accP[0]); accP[1] = f2fma(wvP, p0.y, accP[1]);
        accP[2] = f2fma(wvP, p1.x, accP[2]); accP[3] = f2fma(wvP, p1.y, accP[3]);
        accP[4] = f2fma(wvP, p2.x, accP[4]); accP[5] = f2fma(wvP, p2.y, accP[5]);
        accP[6] = f2fma(wvP, p3.x, accP[6]); accP[7] = f2fma(wvP, p3.y, accP[7]);
    }
    if (mat < 2) {
        __nv_bfloat16* ob = (mat==0) ? g_q2b : g_k2b;
        float sc = (mat==0) ? 0.125f : 1.f;
        #pragma unroll
        for (int j = 0; j < 8; j++) {
            float a0, a1; upk(accP[j], a0, a1);
            ob[(size_t)(n0+2*j)*COUT + col]   = __float2bfloat16(a0*sc);
            ob[(size_t)(n0+2*j+1)*COUT + col] = __float2bfloat16(a1*sc);
        }
    } else {
        float* o = (mat==2) ? g_v2 : g_s2;
        #pragma unroll
        for (int j = 0; j < 8; j++) {
            float a0, a1; upk(accP[j], a0, a1);
            o[(size_t)(n0+2*j)*COUT + col]   = a0;
            o[(size_t)(n0+2*j+1)*COUT + col] = a1;
        }
    }
}

// ---------------- t tables (bf16 in/out) --------------------------------------
__global__ void k_t1(const float* __restrict__ We1) {
    int h = blockIdx.y;
    __shared__ float Wt[32][65];
    __shared__ float qsm[32][33];
    int tid = threadIdx.x;
    for (int i = tid; i < 64*32; i += 256) {
        int d = i >> 5, c = i & 31;
        Wt[c][d] = We1[(size_t)d*128 + h*32 + c];
    }
    int n0 = blockIdx.x * 32;
    for (int i = tid; i < 32*32; i += 256) {
        int nn = i >> 5, c = i & 31;
        qsm[nn][c] = (n0+nn < NN)
            ? __bfloat162float(g_q1b[(size_t)(n0+nn)*128 + h*32 + c]) : 0.f;
    }
    __syncthreads();
    int d = tid & 63, nb = tid >> 6;
    #pragma unroll
    for (int p = 0; p < 8; p++) {
        int nn = p*4 + nb;
        float acc = 0.f;
        #pragma unroll
        for (int c = 0; c < 32; c++) acc += qsm[nn][c] * Wt[c][d];
        if (n0+nn < NN) g_t1b[(size_t)(n0+nn)*256 + h*64 + d] = __float2bfloat16(acc);
    }
}

__global__ void k_t2(const float* __restrict__ We2) {
    __shared__ float Wt[64][65];
    __shared__ float qsm[32][65];
    int tid = threadIdx.x;
    for (int i = tid; i < 64*64; i += 256) {
        int d = i >> 6, c = i & 63;
        Wt[c][d] = We2[(size_t)d*64 + c];
    }
    int n0 = blockIdx.x * 32;
    for (int i = tid; i < 32*64; i += 256) {
        int nn = i >> 6, c = i & 63;
        qsm[nn][c] = (n0+nn < NN)
            ? __bfloat162float(g_q2b[(size_t)(n0+nn)*64 + c]) : 0.f;
    }
    __syncthreads();
    int d = tid & 63, nb = tid >> 6;
    #pragma unroll
    for (int p = 0; p < 8; p++) {
        int nn = p*4 + nb;
        float acc = 0.f;
        #pragma unroll
        for (int c = 0; c < 64; c++) acc += qsm[nn][c] * Wt[c][d];
        if (n0+nn < NN) g_t2b[(size_t)(n0+nn)*64 + d] = __float2bfloat16(acc);
    }
}

// ---------------- layer-1 scores: edge-parallel, bf16 dot --------------------
__global__ void __launch_bounds__(256) k_score1(const float* __restrict__ ef) {
    int tid  = threadIdx.x;
    int lane = tid & 31;
    int l8   = lane & 7;
    int i    = blockIdx.x*32 + (tid >> 3);   // EE % 32 == 0
    if (i >= EE) return;

    int2 se = g_edges[i];
    int  dn = g_edst[i];
    const uint2* kp = (const uint2*)(g_k1b + (size_t)se.x*128);
    const uint2* qp = (const uint2*)(g_q1b + (size_t)dn*128);
    const uint4* tp = (const uint4*)(g_t1b + (size_t)dn*256);
    const float4* ep = (const float4*)(ef + (size_t)se.y*64);

    float4 f0 = ldcs4f(ep + l8*2), f1 = ldcs4f(ep + l8*2 + 1);
    u32 e01 = f2bf2(f0.x, f0.y), e23 = f2bf2(f0.z, f0.w);
    u32 e45 = f2bf2(f1.x, f1.y), e67 = f2bf2(f1.z, f1.w);

    float s[4];
    #pragma unroll
    for (int h = 0; h < 4; h++) {
        uint2 kv = kp[h*8 + l8];
        uint2 qv = qp[h*8 + l8];
        u32 a = bffma2(kv.x, qv.x, 0u);
        a = bffma2(kv.y, qv.y, a);
        uint4 tv = tp[h*8 + l8];
        a = bffma2(e01, tv.x, a);
        a = bffma2(e23, tv.y, a);
        a = bffma2(e45, tv.z, a);
        a = bffma2(e67, tv.w, a);
        s[h] = bfsum2(a);
    }
    #pragma unroll
    for (int o = 1; o <= 4; o <<= 1) {
        s[0] += __shfl_xor_sync(FULL, s[0], o);
        s[1] += __shfl_xor_sync(FULL, s[1], o);
        s[2] += __shfl_xor_sync(FULL, s[2], o);
        s[3] += __shfl_xor_sync(FULL, s[3], o);
    }
    if (l8 == 0) {
        float4 w4;
        w4.x = __expf(s[0]); w4.y = __expf(s[1]);
        w4.z = __expf(s[2]); w4.w = __expf(s[3]);
        *(float4*)(g_w + (size_t)i*4) = w4;
    }
}

// ---------------- layer-1 aggregate (fp32, R8) ---------------------------------
__global__ void __launch_bounds__(256) k_agg1(const float* __restrict__ ef,
                                              const float* __restrict__ We1) {
    int lane = threadIdx.x & 31;
    int wl   = threadIdx.x >> 5;
    int n    = blockIdx.x*8 + wl;
    __shared__ float smemAll[8*384];
    float* aux = smemAll + wl*384;
    float* gsm = aux + 128;
    if (n >= NN) return;

    int l8 = lane & 7, grp = lane >> 3;
    u64t accv0 = 0ull, accv1 = 0ull;
    u64t ag[4] = {0ull,0ull,0ull,0ull};
    float den = 0.f;

    int rs = g_rowptr[n], re = g_rowptr[n+1];
    for (int base = rs; base < re; base += 32) {
        int cnt = min(32, re - base);
        int2 se = make_int2(0, 0);
        if (lane < cnt) {
            se = g_edges[base + lane];
            *(float4*)(aux + lane*4) = *(const float4*)(g_w + (size_t)(base+lane)*4);
        }
        __syncwarp();
        #pragma unroll 2
        for (int e = 0; e < cnt; e++) {
            int esrc = __shfl_sync(FULL, se.x, e);
            int eeid = __shfl_sync(FULL, se.y, e);
            const float* we = aux + e*4;
            float w0 = we[0], w1 = we[1], w2 = we[2], w3 = we[3];
            float wg = (grp==0)?w0:((grp==1)?w1:((grp==2)?w2:w3));
            den += wg;
            u64t wgP = pk(wg, wg);
            ulonglong2 vv = ((const ulonglong2*)(g_v1 + (size_t)esrc*128))[lane];
            accv0 = f2fma(wgP, vv.x, accv0);
            accv1 = f2fma(wgP, vv.y, accv1);
            u64t ev = ldcs1((const u64t*)(ef + (size_t)eeid*64) + lane);
            ag[0] = f2fma(pk(w0,w0), ev, ag[0]);
            ag[1] = f2fma(pk(w1,w1), ev, ag[1]);
            ag[2] = f2fma(pk(w2,w2), ev, ag[2]);
            ag[3] = f2fma(pk(w3,w3), ev, ag[3]);
        }
        __syncwarp();
    }

    u64t* gU = (u64t*)gsm;
    gU[0*32 + lane] = ag[0];
    gU[1*32 + lane] = ag[1];
    gU[2*32 + lane] = ag[2];
    gU[3*32 + lane] = ag[3];
    __syncwarp();

    float4 og = make_float4(0.f,0.f,0.f,0.f);
    const float* Wc = We1 + grp*32 + l8*4;
    const float* gh = gsm + grp*64;
    #pragma unroll 8
    for (int d = 0; d < 64; d++) {
        float g = gh[d];
        float4 wr = *(const float4*)(Wc + (size_t)d*128);
        og.x += g*wr.x; og.y += g*wr.y; og.z += g*wr.z; og.w += g*wr.w;
    }
    float inv = (den > 0.f) ? (1.f/den) : 0.f;
    float4 av; upk(accv0, av.x, av.y); upk(accv1, av.z, av.w);
    float4 skip = *(const float4*)(g_h + (size_t)n*128 + lane*4);
    float4 o;
    o.x = fmaxf(fmaf(av.x + og.x, inv, skip.x), 0.f);
    o.y = fmaxf(fmaf(av.y + og.y, inv, skip.y), 0.f);
    o.z = fmaxf(fmaf(av.z + og.z, inv, skip.z), 0.f);
    o.w = fmaxf(fmaf(av.w + og.w, inv, skip.w), 0.f);
    *(float4*)(g_h + (size_t)n*128 + lane*4) = o;
}

// ---------------- layer-2 scores: edge-parallel, bf16 dot ---------------------
__global__ void __launch_bounds__(256) k_score2(const float* __restrict__ ef) {
    int tid  = threadIdx.x;
    int lane = tid & 31;
    int l8   = lane & 7;
    int i    = blockIdx.x*32 + (tid >> 3);
    if (i >= EE) return;

    int2 se = g_edges[i];
    int  dn = g_edst[i];
    const uint4* kp = (const uint4*)(g_k2b + (size_t)se.x*64);
    const uint4* qp = (const uint4*)(g_q2b + (size_t)dn*64);
    const uint4* tp = (const uint4*)(g_t2b + (size_t)dn*64);
    const float4* ep = (const float4*)(ef + (size_t)se.y*64);

    float4 f0 = ldcs4f(ep + l8*2), f1 = ldcs4f(ep + l8*2 + 1);
    u32 e01 = f2bf2(f0.x, f0.y), e23 = f2bf2(f0.z, f0.w);
    u32 e45 = f2bf2(f1.x, f1.y), e67 = f2bf2(f1.z, f1.w);

    uint4 kv = kp[l8], qv = qp[l8], tv = tp[l8];
    u32 a = bffma2(kv.x, qv.x, 0u);
    a = bffma2(kv.y, qv.y, a);
    a = bffma2(kv.z, qv.z, a);
    a = bffma2(kv.w, qv.w, a);
    a = bffma2(e01, tv.x, a);
    a = bffma2(e23, tv.y, a);
    a = bffma2(e45, tv.z, a);
    a = bffma2(e67, tv.w, a);
    float s = bfsum2(a);
    s += __shfl_xor_sync(FULL, s, 1);
    s += __shfl_xor_sync(FULL, s, 2);
    s += __shfl_xor_sync(FULL, s, 4);
    if (l8 == 0) g_w[i] = __expf(s);
}

// ---------------- layer-2 aggregate (fp32, R8) ----------------------------------
__global__ void __launch_bounds__(256) k_agg2(const float* __restrict__ ef,
                                              const float* __restrict__ We2,
                                              float* __restrict__ out) {
    int lane = threadIdx.x & 31;
    int wl   = threadIdx.x >> 5;
    int n    = blockIdx.x*8 + wl;
    __shared__ float smemAll[8*96];
    float* aux = smemAll + wl*96;
    float* gsm = aux + 32;
    if (n >= NN) return;

    u64t accv = 0ull;
    u64t ag   = 0ull;
    float den = 0.f;
    int rs = g_rowptr[n], re = g_rowptr[n+1];

    for (int base = rs; base < re; base += 32) {
        int cnt = min(32, re - base);
        int2 se = make_int2(0, 0);
        if (lane < cnt) {
            se = g_edges[base + lane];
            aux[lane] = g_w[base + lane];
        }
        __syncwarp();
        #pragma unroll 2
        for (int e = 0; e < cnt; e++) {
            int esrc = __shfl_sync(FULL, se.x, e);
            int eeid = __shfl_sync(FULL, se.y, e);
            float w = aux[e];
            den += w;
            u64t wP = pk(w, w);
            u64t vv = ((const u64t*)(g_v2 + (size_t)esrc*64))[lane];
            accv = f2fma(wP, vv, accv);
            u64t ev = ldcs1((const u64t*)(ef + (size_t)eeid*64) + lane);
            ag = f2fma(wP, ev, ag);
        }
        __syncwarp();
    }

    ((u64t*)gsm)[lane] = ag;
    __syncwarp();

    float2 og = make_float2(0.f,0.f);
    const float* Wc = We2 + lane*2;
    #pragma unroll 8
    for (int d = 0; d < 64; d++) {
        float g = gsm[d];
        float2 wr = *(const float2*)(Wc + (size_t)d*64);
        og.x += g*wr.x; og.y += g*wr.y;
    }
    float inv = (den > 0.f) ? (1.f/den) : 0.f;
    float2 av; upk(accv, av.x, av.y);
    float2 s2 = *(const float2*)(g_s2 + (size_t)n*64 + lane*2);
    float2 o;
    o.x = fmaf(av.x + og.x, inv, s2.x);
    o.y = fmaf(av.y + og.y, inv, s2.y);
    *(float2*)(out + (size_t)n*64 + lane*2) = o;
}

// ---------------- launch -------------------------------------------------------
extern "C" void kernel_launch(void* const* d_in, const int* in_sizes, int n_in,
                              void* d_out, int out_size)
{
    const float* x   = (const float*)d_in[0];
    const float* ef  = (const float*)d_in[1];
    const int*   ei  = (const int*)  d_in[2];
    const float *Wq1 = (const float*)d_in[3],  *bq1 = (const float*)d_in[4];
    const float *Wk1 = (const float*)d_in[5],  *bk1 = (const float*)d_in[6];
    const float *Wv1 = (const float*)d_in[7],  *bv1 = (const float*)d_in[8];
    const float *We1 = (const float*)d_in[9];
    const float *Ws1 = (const float*)d_in[10], *bs1 = (const float*)d_in[11];
    const float *Wq2 = (const float*)d_in[12], *bq2 = (const float*)d_in[13];
    const float *Wk2 = (const float*)d_in[14], *bk2 = (const float*)d_in[15];
    const float *Wv2 = (const float*)d_in[16], *bv2 = (const float*)d_in[17];
    const float *We2 = (const float*)d_in[18];
    const float *Ws2 = (const float*)d_in[19], *bs2 = (const float*)d_in[20];
    float* out = (float*)d_out;

    const int* srcp = ei;
    const int* dstp = ei + EE;

    // CSR build
    k_zero_cnt<<<(NN+255)/256, 256>>>();
    k_hist    <<<(EE+255)/256, 256>>>(dstp);
    k_scanA   <<<49, 1024>>>();
    k_scanB   <<<1, 64>>>();
    k_scanC   <<<(NN+255)/256, 256>>>();
    k_scatter <<<(EE+255)/256, 256>>>(srcp, dstp);

    // layer 1
    dim3 g1(NN/16, 4);
    k_node1 <<<g1, 128>>>(x, Wq1,bq1, Wk1,bk1, Wv1,bv1, Ws1,bs1);
    dim3 gt1((NN+31)/32, 4);
    k_t1    <<<gt1, 256>>>(We1);
    k_score1<<<EE/32, 256>>>(ef);
    k_agg1  <<<(NN+7)/8, 256>>>(ef, We1);

    // layer 2
    k_node2 <<<g1, 64>>>(Wq2,bq2, Wk2,bk2, Wv2,bv2, Ws2,bs2);
    k_t2    <<<(NN+31)/32, 256>>>(We2);
    k_score2<<<EE/32, 256>>>(ef);
    k_agg2  <<<(NN+7)/8, 256>>>(ef, We2, out);
}